// round 7
// baseline (speedup 1.0000x reference)
#include <cuda_runtime.h>
#include <cuda_pipeline.h>
#include <cstdint>

#define TS 1460
#define NG 2000
#define NH 1000      // each scan thread handles cells g and g+NH
#define NREC 24      // floats per (t,g) record
#define TCH 16       // timesteps per routing thread

// ---- scratch (static __device__ globals; no allocation at launch time) ----
__device__ float         g_pre [(size_t)TS * NG * NREC];   // ~280 MB
__device__ unsigned char g_gate[(size_t)TS * NG];
__device__ float         g_surf[(size_t)TS * NG];
__device__ float         g_base[(size_t)TS * NG];
__device__ float         g_uh  [2 * 15 * NG];

__constant__ float c_lo[32] = {0.f,0.5f,0.001f,0.3f,20.f,-8.f,1.f,0.1f,0.1f,1e-4f,1.f,1e-4f,0.1f,0.1f,50.f,-8.f,
                               1.f,-5.f,0.f,1.5f,0.f,0.01f,-1.f,0.f,0.f,0.f,50.f,50.f,0.3f,0.01f,0.5f,0.15f};
__constant__ float c_hi[32] = {1.f,3.f,3.f,1.f,300.f,-2.f,5.f,200.f,0.5f,0.9999f,50.f,0.9999f,50.f,100.f,500.f,-2.f,
                               5.f,2.f,5.f,3.f,5.f,0.2f,1.f,0.4f,1.f,1.f,500.f,500.f,20.f,5.f,13.f,1.5f};

__device__ __forceinline__ float sigm(float x) { return 1.f / (1.f + __expf(-x)); }
__device__ __forceinline__ float clip01(float x) { return fminf(fmaxf(x, 1e-6f), 1.f); }
__device__ __forceinline__ void prefetchL2(const void* p) {
    asm volatile("prefetch.global.L2 [%0];" :: "l"(p));
}
// expm1 for x in [0, 0.5]: Horner, rel err < 4e-6. No MUFU, no call.
__device__ __forceinline__ float expm1_poly(float x) {
    float r = 1.f/720.f;
    r = fmaf(r, x, 1.f/120.f);
    r = fmaf(r, x, 1.f/24.f);
    r = fmaf(r, x, 1.f/6.f);
    r = fmaf(r, x, 0.5f);
    r = fmaf(r, x, 1.f);
    return r * x;
}

// ============================================================================
// Kernel 1: per-(t,g) preprocess
// ============================================================================
__global__ void prep_kernel(const float* __restrict__ xphy, const float* __restrict__ wts) {
    size_t i = (size_t)blockIdx.x * blockDim.x + threadIdx.x;
    if (i >= (size_t)TS * NG) return;
    const float4* wsrc = (const float4*)(wts + i * 24);
    float v[24];
#pragma unroll
    for (int k = 0; k < 6; k++) {
        float4 q = wsrc[k];
        v[4*k] = q.x; v[4*k+1] = q.y; v[4*k+2] = q.z; v[4*k+3] = q.w;
    }
    float out[24];
#pragma unroll
    for (int grp = 0; grp < 3; grp++) {
        float m = v[grp*6];
#pragma unroll
        for (int k = 1; k < 6; k++) m = fmaxf(m, v[grp*6 + k]);
        float e[6], s = 0.f;
#pragma unroll
        for (int k = 0; k < 6; k++) { e[k] = __expf(v[grp*6 + k] - m); s += e[k]; }
        float inv = 1.f / s;
#pragma unroll
        for (int k = 0; k < 6; k++) out[grp*6 + k] = e[k] * inv;
    }
    unsigned bits = 0;
#pragma unroll
    for (int k = 0; k < 6; k++) bits |= (v[18 + k] > 0.f) ? (1u << k) : 0u;
    out[18] = xphy[i*3 + 0];
    out[19] = xphy[i*3 + 1];
    out[20] = xphy[i*3 + 2];
    out[21] = __uint_as_float(bits);
    out[22] = 0.f; out[23] = 0.f;
    float4* dst = (float4*)(g_pre + i * NREC);
#pragma unroll
    for (int k = 0; k < 6; k++) dst[k] = make_float4(out[4*k], out[4*k+1], out[4*k+2], out[4*k+3]);
    g_gate[i] = (unsigned char)bits;
}

// ============================================================================
// Kernel 2: per-cell unit-hydrograph weights
// ============================================================================
__global__ void uh_kernel(const float* __restrict__ hyb) {
    int g = blockIdx.x * blockDim.x + threadIdx.x;
    if (g >= NG) return;
    const float* h = hyb + (size_t)g * 32;
    float a1 = c_lo[28] + sigm(h[28]) * (c_hi[28] - c_lo[28]);
    float b1 = c_lo[29] + sigm(h[29]) * (c_hi[29] - c_lo[29]);
    float a2 = c_lo[30] + sigm(h[30]) * (c_hi[30] - c_lo[30]);
    float b2 = c_lo[31] + sigm(h[31]) * (c_hi[31] - c_lo[31]);
    float ib1 = 1.f / b1, ib2 = 1.f / b2;
    float lw1[15], lw2[15], m1 = -1e30f, m2 = -1e30f;
#pragma unroll
    for (int k = 0; k < 15; k++) {
        float kk = (float)(k + 1);
        float lk = __logf(kk);
        lw1[k] = (a1 - 1.f) * lk - kk * ib1;
        lw2[k] = (a2 - 1.f) * lk - kk * ib2;
        m1 = fmaxf(m1, lw1[k]); m2 = fmaxf(m2, lw2[k]);
    }
    float e1[15], e2[15], s1 = 0.f, s2 = 0.f;
#pragma unroll
    for (int k = 0; k < 15; k++) {
        e1[k] = __expf(lw1[k] - m1); s1 += e1[k];
        e2[k] = __expf(lw2[k] - m2); s2 += e2[k];
    }
    float i1 = 1.f / s1, i2 = 1.f / s2;
#pragma unroll
    for (int k = 0; k < 15; k++) {
        g_uh[k * NG + g]        = e1[k] * i1;
        g_uh[(15 + k) * NG + g] = e2[k] * i2;
    }
}

// ============================================================================
// Scan support: per-cell constants and one branch-free step
// ============================================================================
struct CC {
    float cc, Tbf, Kf, ddfmin, ddfplus, Kcum, Tbm, swi;
    float msw1, inv_m1, inv_m2;
    float inf_pc, hbv_beta, vic_b, hm_a;
    float perc_coef, perc_sfc, crise;
    float inv_x3a, p10a, bfn1, bfmax1, lam, c_lam, thresh, c_th;
    float inv_x3b, p10b, bfn2, bfmax2;
};

__device__ __forceinline__ void load_consts(const float* __restrict__ h, CC& c) {
    float P[32];
#pragma unroll
    for (int i = 0; i < 32; i++) P[i] = c_lo[i] + sigm(h[i]) * (c_hi[i] - c_lo[i]);
    c.cc = P[24] * (1.f - P[25]);
    c.Tbf = P[17]; c.Kf = P[18]; c.ddfmin = P[19]; c.ddfplus = P[20];
    c.Kcum = P[21]; c.Tbm = P[22]; c.swi = P[23];
    c.msw1 = P[26]; c.inv_m1 = 1.f / P[26]; c.inv_m2 = 1.f / P[27];
    c.inf_pc = P[0]; c.hbv_beta = P[1]; c.vic_b = P[2]; c.hm_a = P[3];
    c.perc_coef = P[10] / (1.f - P[11]); c.perc_sfc = P[11]; c.crise = P[12];
    c.inv_x3a = 1.f / P[4];
    c.p10a = exp2f(P[5] * 3.3219280948873623f);
    c.bfn1 = P[6]; c.bfmax1 = P[7]; c.lam = P[8];
    c.c_lam = P[7] / expm1f(P[8]);
    c.thresh = P[9]; c.c_th = P[7] / (1.f - P[9]);
    c.inv_x3b = 1.f / P[14];
    c.p10b = exp2f(P[15] * 3.3219280948873623f);
    c.bfn2 = P[16]; c.bfmax2 = P[13];
}

__device__ __forceinline__ void cell_step(
    const CC& c, float& snow, float& liq, float& cum, float& sw1, float& sw2,
    const float4& c0, const float4& c1, const float4& c2,
    const float4& c3, const float4& c4, const float4& c5,
    float& surf_o, float& base_o)
{
    const float prcp = c4.z, temp = c4.w, pet = c5.x;
    const unsigned bits = __float_as_uint(c5.y);
    const float gb0 = (bits & 1u)        ? 1.f : 0.f;
    const float gb1 = ((bits >> 1) & 1u) ? 1.f : 0.f;
    const float gb2 = ((bits >> 2) & 1u) ? 1.f : 0.f;
    const float gb3 = ((bits >> 3) & 1u) ? 1.f : 0.f;

    // --- snow module ---
    float rain  = (temp >= 0.f) ? prcp : 0.f;
    float snowf = (temp <  0.f) ? prcp : 0.f;
    float canopy = pet * c.cc;
    rain  = fmaxf(rain  - canopy * gb2, 0.f);
    snowf = fmaxf(snowf - canopy * gb3, 0.f);
    float refreeze = fminf(liq, c.Kf * fmaxf(c.Tbf - temp, 0.f));
    snow = snow + snowf + refreeze;
    liq  = liq - refreeze;
    float ddf  = c.ddfmin + c.ddfplus * (1.f - __expf(-c.Kcum * cum));
    float melt = fminf(snow, ddf * fmaxf(temp - c.Tbm, 0.f));
    snow -= melt;
    cum = (snow < 1e-6f) ? 1e-6f : (cum + melt);
    liq += melt;
    float overflow = fmaxf(liq - c.swi * snow, 0.f);
    liq -= overflow;
    float wavail = rain + overflow;

    // --- infiltration blend ---
    float sat1 = clip01(sw1 * c.inv_m1);
    float dry1 = clip01(1.f - sat1);
    float o1 = 1.f - __powf(sat1, c.hbv_beta);
    float o2 = __powf(dry1, c.vic_b);
    float fsum = c0.x * c.inf_pc + c0.y * o1 + c0.z * o2 + c0.w * (c.hm_a * dry1)
               + c1.x * (1.f - sat1 * sat1) + c1.y;
    float infil = wavail * fsum;
    sw1 += infil;
    float excess = fmaxf(sw1 - c.msw1, 0.f);
    sw1 -= excess;
    float surf = wavail - infil + excess;

    // --- percolation / capillary rise / ET ---
    sat1 = clip01(sw1 * c.inv_m1);
    float perc = gb0 * c.perc_coef * fmaxf(sat1 - c.perc_sfc, 0.f);
    perc = fminf(perc, sw1);
    sw1 -= perc; sw2 += perc;
    float sat2 = clip01(sw2 * c.inv_m2);
    sat1 = clip01(sw1 * c.inv_m1);
    float capi = fminf(gb1 * c.crise * (1.f - sat1) * sat2, sw2);
    sw2 -= capi; sw1 += capi;
    sat1 = clip01(sw1 * c.inv_m1);
    float et = fminf(pet * sat1, sw1);
    sw1 -= et;
    sat1 = clip01(sw1 * c.inv_m1);

    // --- baseflow 1 blend ---   (1+r^4)^(-1/4) == sqrtf(rsqrtf(q))
    float ra = sw1 * c.inv_x3a; float ra2 = ra * ra; float qa = 1.f + ra2 * ra2;
    float b0v = sw1 * (1.f - sqrtf(rsqrtf(qa)));
    float b1v = c.p10a * sw1;
    float b2v = c.bfmax1 * __powf(sat1, c.bfn1);
    float b3v = c.bfmax1 * sat1;
    float b4v = c.c_lam * expm1_poly(c.lam * sat1);
    float b5v = c.c_th * fmaxf(sat1 - c.thresh, 0.f);
    float bf1 = fminf(c1.z*b0v + c1.w*b1v + c2.x*b2v + c2.y*b3v + c2.z*b4v + c2.w*b5v, sw1);
    sw1 -= bf1;

    // --- baseflow 2 blend ---
    float s2c = clip01(sw2 * c.inv_m2);
    float rb = sw2 * c.inv_x3b; float rb2 = rb * rb; float qb = 1.f + rb2 * rb2;
    float d0 = sw2 * (1.f - sqrtf(rsqrtf(qb)));
    float d1 = c.p10b * sw2;
    float d2 = c.bfmax2 * __powf(s2c, c.bfn2);
    float d3 = c.bfmax2 * s2c;
    float d4 = c.bfmax2 * s2c * s2c;
    float d5 = d1 * s2c;
    float bf2 = fminf(c3.x*d0 + c3.y*d1 + c3.z*d2 + c3.w*d3 + c4.x*d4 + c4.y*d5, sw2);
    sw2 -= bf2;

    surf_o = surf;
    base_o = bf1 + bf2;
}

// ============================================================================
// Kernel 3: sequential scan, TWO interleaved cells per thread, with a
// 3-stage cp.async (LDGSTS) shared-memory pipeline. Records stream
// GMEM->SMEM with ZERO register cost; the loop reads them via 29-cycle LDS.
// One warp per block, each thread reads only its own smem slots -> no bar.
// ============================================================================
__global__ void __launch_bounds__(32) scan_kernel(const float* __restrict__ hyb) {
    // pad to 13 float4 per lane-row: lane stride 208B -> conflict-free LDS.128
    __shared__ float4 sbuf[3][32][13];

    const int lane = threadIdx.x;
    const int gidx = blockIdx.x * 32 + lane;
    const bool act = (gidx < NH);
    const int gA = act ? gidx : (NH - 1);
    const int gB = gA + NH;
    const int wbA = blockIdx.x * 32;
    const int wbB = wbA + NH;

    CC cA, cB;
    load_consts(hyb + (size_t)gA * 32, cA);
    load_consts(hyb + (size_t)gB * 32, cB);

    float snowA=1e-6f, liqA=1e-6f, cumA=1e-6f, sw1A=1e-6f, sw2A=1e-6f;
    float snowB=1e-6f, liqB=1e-6f, cumB=1e-6f, sw1B=1e-6f, sw2B=1e-6f;

    const float4* rec = (const float4*)g_pre;
    const char* pf_lim = (const char*)g_pre + sizeof(float) * (size_t)TS * NG * NREC - 128;

    // prologue: stage records for t=0 and t=1
#pragma unroll
    for (int tp = 0; tp < 2; tp++) {
        const float4* srcA = rec + ((size_t)tp * NG + gA) * 6;
        const float4* srcB = rec + ((size_t)tp * NG + gB) * 6;
#pragma unroll
        for (int k = 0; k < 6; k++) {
            __pipeline_memcpy_async(&sbuf[tp][lane][k],     srcA + k, 16);
            __pipeline_memcpy_async(&sbuf[tp][lane][6 + k], srcB + k, 16);
        }
        __pipeline_commit();
    }
    // prime L2 for the next several steps (warp-cooperative lane-strided lines)
#pragma unroll
    for (int tp = 2; tp < 10; tp++) {
        const char* pA = (const char*)(rec + ((size_t)tp * NG + wbA) * 6) + lane * 128;
        const char* pB = (const char*)(rec + ((size_t)tp * NG + wbB) * 6) + lane * 128;
        prefetchL2(pA < pf_lim ? pA : pf_lim);
        prefetchL2(pB < pf_lim ? pB : pf_lim);
    }

    for (int t = 0; t < TS; t++) {
        // L2 prefetch 10 steps ahead (keeps the LDGSTS below as L2 hits)
        int tpf = t + 10; if (tpf >= TS) tpf = TS - 1;
        {
            const char* pA = (const char*)(rec + ((size_t)tpf * NG + wbA) * 6) + lane * 128;
            const char* pB = (const char*)(rec + ((size_t)tpf * NG + wbB) * 6) + lane * 128;
            prefetchL2(pA < pf_lim ? pA : pf_lim);
            prefetchL2(pB < pf_lim ? pB : pf_lim);
        }

        // wait until the group for step t has landed, then read via LDS
        __pipeline_wait_prior(1);
        const int s = t % 3;
        float4 a0 = sbuf[s][lane][0],  a1 = sbuf[s][lane][1],  a2 = sbuf[s][lane][2],
               a3 = sbuf[s][lane][3],  a4 = sbuf[s][lane][4],  a5 = sbuf[s][lane][5];
        float4 b0 = sbuf[s][lane][6],  b1 = sbuf[s][lane][7],  b2 = sbuf[s][lane][8],
               b3 = sbuf[s][lane][9],  b4 = sbuf[s][lane][10], b5 = sbuf[s][lane][11];

        // stage step t+2 into ring slot (t+2)%3 (that slot was read at t-1)
        int t2 = t + 2; if (t2 >= TS) t2 = TS - 1;
        const int s2 = (t + 2) % 3;
        {
            const float4* srcA = rec + ((size_t)t2 * NG + gA) * 6;
            const float4* srcB = rec + ((size_t)t2 * NG + gB) * 6;
#pragma unroll
            for (int k = 0; k < 6; k++) {
                __pipeline_memcpy_async(&sbuf[s2][lane][k],     srcA + k, 16);
                __pipeline_memcpy_async(&sbuf[s2][lane][6 + k], srcB + k, 16);
            }
            __pipeline_commit();
        }

        float surfA, baseA, surfB, baseB;
        cell_step(cA, snowA, liqA, cumA, sw1A, sw2A, a0,a1,a2,a3,a4,a5, surfA, baseA);
        cell_step(cB, snowB, liqB, cumB, sw1B, sw2B, b0,b1,b2,b3,b4,b5, surfB, baseB);

        if (act) {
            size_t o = (size_t)t * NG;
            g_surf[o + gA] = surfA;  g_base[o + gA] = baseA;
            g_surf[o + gB] = surfB;  g_base[o + gB] = baseB;
        }
    }
}

// ============================================================================
// Kernel 4: 15-tap UH routing + gating + final sum.
// ============================================================================
__global__ void __launch_bounds__(128) route_kernel(float* __restrict__ out) {
    int g  = blockIdx.x * 128 + threadIdx.x;
    int t0 = blockIdx.y * TCH;
    if (g >= NG) return;
    float u1[15], u2[15];
#pragma unroll
    for (int k = 0; k < 15; k++) {
        u1[k] = g_uh[k * NG + g];
        u2[k] = g_uh[(15 + k) * NG + g];
    }
    float s[TCH + 14], b[TCH + 14];
#pragma unroll
    for (int i = 0; i < TCH + 14; i++) {
        int tt = t0 - 14 + i;
        bool ok = (tt >= 0) && (tt < TS);
        s[i] = ok ? g_surf[(size_t)tt * NG + g] : 0.f;
        b[i] = ok ? g_base[(size_t)tt * NG + g] : 0.f;
    }
#pragma unroll
    for (int j = 0; j < TCH; j++) {
        int t = t0 + j;
        if (t < TS) {
            float cs = 0.f, cb = 0.f;
#pragma unroll
            for (int l = 0; l < 15; l++) {
                cs += u1[l] * s[14 + j - l];
                cb += u2[l] * b[14 + j - l];
            }
            unsigned bits = g_gate[(size_t)t * NG + g];
            float g4 = (float)((bits >> 4) & 1);
            float g5 = (float)((bits >> 5) & 1);
            out[(size_t)t * NG + g] = g4 * cs + (1.f - g4) * s[14 + j]
                                    + g5 * cb + (1.f - g5) * b[14 + j];
        }
    }
}

// ============================================================================
extern "C" void kernel_launch(void* const* d_in, const int* in_sizes, int n_in,
                              void* d_out, int out_size) {
    const float* xphy = nullptr; const float* wts = nullptr; const float* hyb = nullptr;
    for (int i = 0; i < n_in; i++) {
        if (in_sizes[i] == TS * NG * 3)       xphy = (const float*)d_in[i];
        else if (in_sizes[i] == TS * NG * 24) wts  = (const float*)d_in[i];
        else if (in_sizes[i] == NG * 32)      hyb  = (const float*)d_in[i];
    }
    float* out = (float*)d_out;                  // (1460, 2000)

    size_t total = (size_t)TS * NG;
    prep_kernel<<<(unsigned)((total + 255) / 256), 256>>>(xphy, wts);
    uh_kernel<<<(NG + 127) / 128, 128>>>(hyb);
    scan_kernel<<<(NH + 31) / 32, 32>>>(hyb);
    dim3 rg((NG + 127) / 128, (TS + TCH - 1) / TCH);
    route_kernel<<<rg, 128>>>(out);
}

// round 9
// speedup vs baseline: 2.6066x; 2.6066x over previous
#include <cuda_runtime.h>
#include <cuda_fp16.h>
#include <cstdint>

#define TS 1460
#define NG 2000
#define NREC 16      // floats per (t,g) record (64B): 9x half2 weights, bits, prcp, temp, pet, pad
#define TCH 16       // timesteps per routing thread

// ---- scratch (static __device__ globals; no allocation at launch time) ----
__device__ float         g_pre [(size_t)TS * NG * NREC];   // ~187 MB
__device__ unsigned char g_gate[(size_t)TS * NG];
__device__ float         g_surf[(size_t)TS * NG];
__device__ float         g_base[(size_t)TS * NG];
__device__ float         g_uh  [2 * 15 * NG];

__constant__ float c_lo[32] = {0.f,0.5f,0.001f,0.3f,20.f,-8.f,1.f,0.1f,0.1f,1e-4f,1.f,1e-4f,0.1f,0.1f,50.f,-8.f,
                               1.f,-5.f,0.f,1.5f,0.f,0.01f,-1.f,0.f,0.f,0.f,50.f,50.f,0.3f,0.01f,0.5f,0.15f};
__constant__ float c_hi[32] = {1.f,3.f,3.f,1.f,300.f,-2.f,5.f,200.f,0.5f,0.9999f,50.f,0.9999f,50.f,100.f,500.f,-2.f,
                               5.f,2.f,5.f,3.f,5.f,0.2f,1.f,0.4f,1.f,1.f,500.f,500.f,20.f,5.f,13.f,1.5f};

__device__ __forceinline__ float sigm(float x) { return 1.f / (1.f + __expf(-x)); }
__device__ __forceinline__ float clip01(float x) { return fminf(fmaxf(x, 1e-6f), 1.f); }
__device__ __forceinline__ void prefetchL2(const void* p) {
    asm volatile("prefetch.global.L2 [%0];" :: "l"(p));
}
// expm1 for x in [0, 0.5]: Horner, rel err < 4e-6.
__device__ __forceinline__ float expm1_poly(float x) {
    float r = 1.f/720.f;
    r = fmaf(r, x, 1.f/120.f);
    r = fmaf(r, x, 1.f/24.f);
    r = fmaf(r, x, 1.f/6.f);
    r = fmaf(r, x, 0.5f);
    r = fmaf(r, x, 1.f);
    return r * x;
}
// reinterpret a float register holding packed half2 -> two floats
__device__ __forceinline__ float2 h2pair(float v) {
    unsigned u = __float_as_uint(v);
    __half2 h = *reinterpret_cast<__half2*>(&u);
    return __half22float2(h);
}
__device__ __forceinline__ unsigned packh2(float a, float b) {
    __half2 h = __floats2half2_rn(a, b);
    return *reinterpret_cast<unsigned*>(&h);
}

// ============================================================================
// Kernel 1: per-(t,g) preprocess — softmax 3 weight groups -> fp16 pairs,
// gate bits, met forcing; 64B record = 4 coalesced LDG.128 in the scan.
// ============================================================================
__global__ void prep_kernel(const float* __restrict__ xphy, const float* __restrict__ wts) {
    size_t i = (size_t)blockIdx.x * blockDim.x + threadIdx.x;
    if (i >= (size_t)TS * NG) return;
    const float4* wsrc = (const float4*)(wts + i * 24);
    float v[24];
#pragma unroll
    for (int k = 0; k < 6; k++) {
        float4 q = wsrc[k];
        v[4*k] = q.x; v[4*k+1] = q.y; v[4*k+2] = q.z; v[4*k+3] = q.w;
    }
    float w[18];
#pragma unroll
    for (int grp = 0; grp < 3; grp++) {
        float m = v[grp*6];
#pragma unroll
        for (int k = 1; k < 6; k++) m = fmaxf(m, v[grp*6 + k]);
        float e[6], s = 0.f;
#pragma unroll
        for (int k = 0; k < 6; k++) { e[k] = __expf(v[grp*6 + k] - m); s += e[k]; }
        float inv = 1.f / s;
#pragma unroll
        for (int k = 0; k < 6; k++) w[grp*6 + k] = e[k] * inv;
    }
    unsigned bits = 0;
#pragma unroll
    for (int k = 0; k < 6; k++) bits |= (v[18 + k] > 0.f) ? (1u << k) : 0u;

    unsigned o[16];
#pragma unroll
    for (int k = 0; k < 9; k++) o[k] = packh2(w[2*k], w[2*k+1]);
    o[9]  = bits;
    o[10] = __float_as_uint(xphy[i*3 + 0]);   // prcp
    o[11] = __float_as_uint(xphy[i*3 + 1]);   // temp
    o[12] = __float_as_uint(xphy[i*3 + 2]);   // pet
    o[13] = 0u; o[14] = 0u; o[15] = 0u;

    float4* dst = (float4*)(g_pre + i * NREC);
#pragma unroll
    for (int k = 0; k < 4; k++)
        dst[k] = make_float4(__uint_as_float(o[4*k]), __uint_as_float(o[4*k+1]),
                             __uint_as_float(o[4*k+2]), __uint_as_float(o[4*k+3]));
    g_gate[i] = (unsigned char)bits;
}

// ============================================================================
// Kernel 2: per-cell unit-hydrograph weights
// ============================================================================
__global__ void uh_kernel(const float* __restrict__ hyb) {
    int g = blockIdx.x * blockDim.x + threadIdx.x;
    if (g >= NG) return;
    const float* h = hyb + (size_t)g * 32;
    float a1 = c_lo[28] + sigm(h[28]) * (c_hi[28] - c_lo[28]);
    float b1 = c_lo[29] + sigm(h[29]) * (c_hi[29] - c_lo[29]);
    float a2 = c_lo[30] + sigm(h[30]) * (c_hi[30] - c_lo[30]);
    float b2 = c_lo[31] + sigm(h[31]) * (c_hi[31] - c_lo[31]);
    float ib1 = 1.f / b1, ib2 = 1.f / b2;
    float lw1[15], lw2[15], m1 = -1e30f, m2 = -1e30f;
#pragma unroll
    for (int k = 0; k < 15; k++) {
        float kk = (float)(k + 1);
        float lk = __logf(kk);
        lw1[k] = (a1 - 1.f) * lk - kk * ib1;
        lw2[k] = (a2 - 1.f) * lk - kk * ib2;
        m1 = fmaxf(m1, lw1[k]); m2 = fmaxf(m2, lw2[k]);
    }
    float e1[15], e2[15], s1 = 0.f, s2 = 0.f;
#pragma unroll
    for (int k = 0; k < 15; k++) {
        e1[k] = __expf(lw1[k] - m1); s1 += e1[k];
        e2[k] = __expf(lw2[k] - m2); s2 += e2[k];
    }
    float i1 = 1.f / s1, i2 = 1.f / s2;
#pragma unroll
    for (int k = 0; k < 15; k++) {
        g_uh[k * NG + g]        = e1[k] * i1;
        g_uh[(15 + k) * NG + g] = e2[k] * i2;
    }
}

// ============================================================================
// Kernel 3: sequential scan over T — R4 structure (1 cell/thread, one warp
// per SM, depth-2 register pipeline + per-lane L2 prefetch), 64B records.
// ============================================================================
__global__ void __launch_bounds__(32, 1) scan_kernel(const float* __restrict__ hyb) {
    int g = blockIdx.x * 32 + threadIdx.x;
    if (g >= NG) return;
    const float* h = hyb + (size_t)g * 32;
    float P[32];
#pragma unroll
    for (int i = 0; i < 32; i++) P[i] = c_lo[i] + sigm(h[i]) * (c_hi[i] - c_lo[i]);

    // per-cell derived constants
    const float cc      = P[24] * (1.f - P[25]);
    const float Tbf = P[17], Kf = P[18], ddfmin = P[19], ddfplus = P[20];
    const float Kcum = P[21], Tbm = P[22], swi = P[23];
    const float msw1 = P[26];
    const float inv_m1 = 1.f / P[26], inv_m2 = 1.f / P[27];
    const float inf_pc = P[0], hbv_beta = P[1], vic_b = P[2], hm_a = P[3];
    const float perc_coef = P[10] / (1.f - P[11]);
    const float perc_sfc = P[11], crise = P[12];
    const float inv_x3a = 1.f / P[4];
    const float p10a = exp2f(P[5] * 3.3219280948873623f);   // 10^bfc1
    const float bfn1 = P[6], bfmax1 = P[7], lam = P[8];
    const float c_lam = bfmax1 / expm1f(lam);
    const float thresh = P[9];
    const float c_th = bfmax1 / (1.f - thresh);
    const float inv_x3b = 1.f / P[14];
    const float p10b = exp2f(P[15] * 3.3219280948873623f);  // 10^bfc2
    const float bfn2 = P[16], bfmax2 = P[13];

    float snow = 1e-6f, liq = 1e-6f, cum = 1e-6f, sw1 = 1e-6f, sw2 = 1e-6f;

    const float4* rec = (const float4*)g_pre;
    size_t r0 = ((size_t)0 * NG + g) * 4;
    size_t r1 = ((size_t)1 * NG + g) * 4;
    // depth-2 pipeline: c* = record[t], n* = record[t+1]
    float4 c0 = __ldcs(rec+r0), c1 = __ldcs(rec+r0+1), c2 = __ldcs(rec+r0+2), c3 = __ldcs(rec+r0+3);
    float4 n0 = __ldcs(rec+r1), n1 = __ldcs(rec+r1+1), n2 = __ldcs(rec+r1+2), n3 = __ldcs(rec+r1+3);
    // prime L2 for the first few steps
#pragma unroll
    for (int tp = 2; tp < 8; tp++)
        prefetchL2((const char*)(rec + ((size_t)tp * NG + g) * 4));

    for (int t = 0; t < TS; t++) {
        // L2 prefetch 8 steps ahead (64B record sits in one 128B line)
        int tpf = t + 8; if (tpf >= TS) tpf = TS - 1;
        prefetchL2((const char*)(rec + ((size_t)tpf * NG + g) * 4));

        // issue loads for t+2 (consumed two bodies later; L2 hits)
        int t2 = t + 2; if (t2 >= TS) t2 = TS - 1;
        size_t r2 = ((size_t)t2 * NG + g) * 4;
        float4 m0 = __ldcs(rec+r2),   m1v = __ldcs(rec+r2+1),
               m2v = __ldcs(rec+r2+2), m3 = __ldcs(rec+r2+3);

        // unpack current record: 9 half2 pairs + bits + met
        float2 pw0 = h2pair(c0.x), pw1 = h2pair(c0.y), pw2 = h2pair(c0.z);
        float2 pa0 = h2pair(c0.w), pa1 = h2pair(c1.x), pa2 = h2pair(c1.y);
        float2 pb0 = h2pair(c1.z), pb1 = h2pair(c1.w), pb2 = h2pair(c2.x);
        const float wi0 = pw0.x, wi1 = pw0.y, wi2 = pw1.x, wi3 = pw1.y, wi4 = pw2.x, wi5 = pw2.y;
        const float wa0 = pa0.x, wa1 = pa0.y, wa2 = pa1.x, wa3 = pa1.y, wa4 = pa2.x, wa5 = pa2.y;
        const float wb0 = pb0.x, wb1 = pb0.y, wb2 = pb1.x, wb3 = pb1.y, wb4 = pb2.x, wb5 = pb2.y;
        const unsigned bits = __float_as_uint(c2.y);
        const float prcp = c2.z, temp = c2.w, pet = c3.x;
        const float gb0 = (bits & 1u)        ? 1.f : 0.f;
        const float gb1 = ((bits >> 1) & 1u) ? 1.f : 0.f;
        const float gb2 = ((bits >> 2) & 1u) ? 1.f : 0.f;
        const float gb3 = ((bits >> 3) & 1u) ? 1.f : 0.f;

        // --- snow module ---
        float rain  = (temp >= 0.f) ? prcp : 0.f;
        float snowf = (temp <  0.f) ? prcp : 0.f;
        float canopy = pet * cc;
        rain  = fmaxf(rain  - canopy * gb2, 0.f);
        snowf = fmaxf(snowf - canopy * gb3, 0.f);
        float refreeze = fminf(liq, Kf * fmaxf(Tbf - temp, 0.f));
        snow = snow + snowf + refreeze;
        liq  = liq - refreeze;
        float ddf  = ddfmin + ddfplus * (1.f - __expf(-Kcum * cum));
        float melt = fminf(snow, ddf * fmaxf(temp - Tbm, 0.f));
        snow -= melt;
        cum = (snow < 1e-6f) ? 1e-6f : (cum + melt);
        liq += melt;
        float overflow = fmaxf(liq - swi * snow, 0.f);
        liq -= overflow;
        float wavail = rain + overflow;

        // --- infiltration blend ---
        float sat1 = clip01(sw1 * inv_m1);
        float dry1 = clip01(1.f - sat1);
        float o1 = 1.f - __powf(sat1, hbv_beta);
        float o2 = __powf(dry1, vic_b);
        float fsum = wi0 * inf_pc + wi1 * o1 + wi2 * o2 + wi3 * (hm_a * dry1)
                   + wi4 * (1.f - sat1 * sat1) + wi5;
        float infil = wavail * fsum;
        sw1 += infil;
        float excess = fmaxf(sw1 - msw1, 0.f);
        sw1 -= excess;
        float surf = wavail - infil + excess;

        // --- percolation / capillary rise / ET ---
        sat1 = clip01(sw1 * inv_m1);
        float perc = gb0 * perc_coef * fmaxf(sat1 - perc_sfc, 0.f);
        perc = fminf(perc, sw1);
        sw1 -= perc; sw2 += perc;
        float sat2 = clip01(sw2 * inv_m2);
        sat1 = clip01(sw1 * inv_m1);
        float capi = fminf(gb1 * crise * (1.f - sat1) * sat2, sw2);
        sw2 -= capi; sw1 += capi;
        sat1 = clip01(sw1 * inv_m1);
        float et = fminf(pet * sat1, sw1);
        sw1 -= et;
        sat1 = clip01(sw1 * inv_m1);

        // --- baseflow 1 blend ---   (1+r^4)^(-1/4) == sqrtf(rsqrtf(q))
        float ra = sw1 * inv_x3a; float ra2 = ra * ra; float qa = 1.f + ra2 * ra2;
        float b0v = sw1 * (1.f - sqrtf(rsqrtf(qa)));
        float b1v = p10a * sw1;
        float b2v = bfmax1 * __powf(sat1, bfn1);
        float b3v = bfmax1 * sat1;
        float b4v = c_lam * expm1_poly(lam * sat1);
        float b5v = c_th * fmaxf(sat1 - thresh, 0.f);
        float bf1 = fminf(wa0*b0v + wa1*b1v + wa2*b2v + wa3*b3v + wa4*b4v + wa5*b5v, sw1);
        sw1 -= bf1;

        // --- baseflow 2 blend ---
        float s2c = clip01(sw2 * inv_m2);
        float rb = sw2 * inv_x3b; float rb2 = rb * rb; float qb = 1.f + rb2 * rb2;
        float d0 = sw2 * (1.f - sqrtf(rsqrtf(qb)));
        float d1 = p10b * sw2;
        float d2 = bfmax2 * __powf(s2c, bfn2);
        float d3 = bfmax2 * s2c;
        float d4 = bfmax2 * s2c * s2c;
        float d5 = d1 * s2c;
        float bf2 = fminf(wb0*d0 + wb1*d1 + wb2*d2 + wb3*d3 + wb4*d4 + wb5*d5, sw2);
        sw2 -= bf2;

        g_surf[(size_t)t * NG + g] = surf;
        g_base[(size_t)t * NG + g] = bf1 + bf2;

        // rotate pipeline
        c0 = n0; c1 = n1; c2 = n2; c3 = n3;
        n0 = m0; n1 = m1v; n2 = m2v; n3 = m3;
    }
}

// ============================================================================
// Kernel 4: 15-tap UH routing + gating + final sum.
// ============================================================================
__global__ void __launch_bounds__(128) route_kernel(float* __restrict__ out) {
    int g  = blockIdx.x * 128 + threadIdx.x;
    int t0 = blockIdx.y * TCH;
    if (g >= NG) return;
    float u1[15], u2[15];
#pragma unroll
    for (int k = 0; k < 15; k++) {
        u1[k] = g_uh[k * NG + g];
        u2[k] = g_uh[(15 + k) * NG + g];
    }
    float s[TCH + 14], b[TCH + 14];
#pragma unroll
    for (int i = 0; i < TCH + 14; i++) {
        int tt = t0 - 14 + i;
        bool ok = (tt >= 0) && (tt < TS);
        s[i] = ok ? g_surf[(size_t)tt * NG + g] : 0.f;
        b[i] = ok ? g_base[(size_t)tt * NG + g] : 0.f;
    }
#pragma unroll
    for (int j = 0; j < TCH; j++) {
        int t = t0 + j;
        if (t < TS) {
            float cs = 0.f, cb = 0.f;
#pragma unroll
            for (int l = 0; l < 15; l++) {
                cs += u1[l] * s[14 + j - l];
                cb += u2[l] * b[14 + j - l];
            }
            unsigned bits = g_gate[(size_t)t * NG + g];
            float g4 = (float)((bits >> 4) & 1);
            float g5 = (float)((bits >> 5) & 1);
            out[(size_t)t * NG + g] = g4 * cs + (1.f - g4) * s[14 + j]
                                    + g5 * cb + (1.f - g5) * b[14 + j];
        }
    }
}

// ============================================================================
extern "C" void kernel_launch(void* const* d_in, const int* in_sizes, int n_in,
                              void* d_out, int out_size) {
    const float* xphy = nullptr; const float* wts = nullptr; const float* hyb = nullptr;
    for (int i = 0; i < n_in; i++) {
        if (in_sizes[i] == TS * NG * 3)       xphy = (const float*)d_in[i];
        else if (in_sizes[i] == TS * NG * 24) wts  = (const float*)d_in[i];
        else if (in_sizes[i] == NG * 32)      hyb  = (const float*)d_in[i];
    }
    float* out = (float*)d_out;                  // (1460, 2000)

    size_t total = (size_t)TS * NG;
    prep_kernel<<<(unsigned)((total + 255) / 256), 256>>>(xphy, wts);
    uh_kernel<<<(NG + 127) / 128, 128>>>(hyb);
    scan_kernel<<<(NG + 31) / 32, 32>>>(hyb);
    dim3 rg((NG + 127) / 128, (TS + TCH - 1) / TCH);
    route_kernel<<<rg, 128>>>(out);
}